// round 17
// baseline (speedup 1.0000x reference)
#include <cuda_runtime.h>
#include <cuda_fp16.h>
#include <math.h>
#include <stdint.h>

// Problem constants (B=2048, A=32, D=128, H=256)
#define NB    2048
#define NA    32
#define NROWS (NB * NA)   // 65536
#define DIN   128
#define HD    256
#define H3    768
#define H4    1024

// ---------------------------------------------------------------------------
// Scratch
// ---------------------------------------------------------------------------
__device__ float g_sg [(size_t)NB * H3];
__device__ float g_bias2[H4];      // interleaved gc2 bias
__device__ float g_bias23[H4];     // interleaved hgh bias
__device__ float g_zero_bias[H3];  // never written -> stays zero

__device__ uint4 g_obs_f  [(size_t)NROWS * DIN / 8];
__device__ uint4 g_e_f    [(size_t)NROWS * HD / 8];
__device__ uint4 g_h1_f   [(size_t)NROWS * HD / 8];
__device__ uint4 g_S_f    [(size_t)NB * HD / 8];
__device__ uint4 g_ew_f   [(size_t)HD * DIN / 8];
__device__ uint4 g_fwT_f  [(size_t)HD * HD / 8];     // fobs_W transposed (fp16)
__device__ uint4 g_wcomb_f[(size_t)H3 * HD / 8];     // W_hh @ fobs_W (fp16)
__device__ uint4 g_w23_f  [(size_t)H4 * HD / 8];     // interleaved [h|gh_r|gh_z|gh_n]
__device__ uint4 g_wih_f  [(size_t)H3 * HD / 8];
__device__ uint4 g_whh_f  [(size_t)H3 * HD / 8];
__device__ uint4 g_wc2_f  [(size_t)H4 * HD / 8];     // interleaved [rz_r|rz_z|Gih_n|h_n]

__device__ __forceinline__ float sigmoidf_(float x) { return 1.0f / (1.0f + expf(-x)); }

__device__ __forceinline__ uint32_t smem_to_u32(const void* p) {
    uint32_t a;
    asm("{ .reg .u64 t; cvta.to.shared.u64 t, %1; cvt.u32.u64 %0, t; }" : "=r"(a) : "l"(p));
    return a;
}

#define SMEM_SWIZZLE_128B(off) ((off) ^ (((off) >> 3) & 0x70))

// ---------------------------------------------------------------------------
// primitives
// ---------------------------------------------------------------------------
__device__ __forceinline__ void mma_f16(float* c, uint32_t a0, uint32_t a1, uint32_t a2,
                                        uint32_t a3, uint32_t b0, uint32_t b1) {
    asm volatile(
        "mma.sync.aligned.m16n8k16.row.col.f32.f16.f16.f32 "
        "{%0,%1,%2,%3}, {%4,%5,%6,%7}, {%8,%9}, {%0,%1,%2,%3};"
        : "+f"(c[0]), "+f"(c[1]), "+f"(c[2]), "+f"(c[3])
        : "r"(a0), "r"(a1), "r"(a2), "r"(a3), "r"(b0), "r"(b1));
}
__device__ __forceinline__ void ldm_x4(uint32_t* r, uint32_t addr) {
    asm volatile("ldmatrix.sync.aligned.m8n8.x4.shared.b16 {%0,%1,%2,%3}, [%4];"
                 : "=r"(r[0]), "=r"(r[1]), "=r"(r[2]), "=r"(r[3]) : "r"(addr));
}
__device__ __forceinline__ void ldm_x2(uint32_t* r, uint32_t addr) {
    asm volatile("ldmatrix.sync.aligned.m8n8.x2.shared.b16 {%0,%1}, [%2];"
                 : "=r"(r[0]), "=r"(r[1]) : "r"(addr));
}
__device__ __forceinline__ void cp16(uint32_t dst, const void* src) {
    asm volatile("cp.async.cg.shared.global [%0], [%1], 16;" :: "r"(dst), "l"(src));
}
#define CP_COMMIT()  asm volatile("cp.async.commit_group;")
#define CP_WAIT(n)   asm volatile("cp.async.wait_group %0;" :: "n"(n))

__device__ __forceinline__ uint32_t pack_h2(float a, float b) {
    __half2 h = __floats2half2_rn(a, b);
    return *reinterpret_cast<uint32_t*>(&h);
}

// ---------------------------------------------------------------------------
// conversions
// ---------------------------------------------------------------------------
__global__ void convert_h(const float4* __restrict__ src, uint2* __restrict__ dst, int n4)
{
    const int i = blockIdx.x * blockDim.x + threadIdx.x;
    if (i >= n4) return;
    float4 v = src[i];
    uint2 o;
    o.x = pack_h2(v.x, v.y);
    o.y = pack_h2(v.z, v.w);
    dst[i] = o;
}

// Weight conversions (float4 units):
//  [0,8192)        ew -> ew_f
//  [8192,57344)    wih -> wih_f
//  [57344,106496)  whh -> whh_f
//  [106496,172032) wc2 interleaved: row nr=(j>>5)*128+seg*32+(j&31)
//      seg0: whh[j]-wih[j]/32 ; seg1: whh[256+j]-wih[256+j]/32
//      seg2: wih[512+j]       ; seg3: whh[512+j]
__global__ void convert_weights(const float4* __restrict__ ew,
                                const float4* __restrict__ wih, const float4* __restrict__ whh,
                                uint2* __restrict__ ew_f,
                                uint2* __restrict__ wih_f, uint2* __restrict__ whh_f,
                                uint2* __restrict__ wc2_f)
{
    const int gid = blockIdx.x * blockDim.x + threadIdx.x;
    float4 v;
    uint2* dst;
    int i;
    if (gid < 8192)        { i = gid;          v = ew[i];  dst = ew_f + i; }
    else if (gid < 57344)  { i = gid - 8192;   v = wih[i]; dst = wih_f + i; }
    else if (gid < 106496) { i = gid - 57344;  v = whh[i]; dst = whh_f + i; }
    else if (gid < 172032) {
        const int t  = gid - 106496;      // 0..65535
        const int nr = t >> 6, c4 = t & 63;
        const int seg = (nr >> 5) & 3;
        const int j = (nr >> 7) * 32 + (nr & 31);
        if (seg == 0) {
            float4 a = whh[j * 64 + c4], b = wih[j * 64 + c4];
            v.x = a.x - b.x * 0.03125f;  v.y = a.y - b.y * 0.03125f;
            v.z = a.z - b.z * 0.03125f;  v.w = a.w - b.w * 0.03125f;
        } else if (seg == 1) {
            float4 a = whh[(256 + j) * 64 + c4], b = wih[(256 + j) * 64 + c4];
            v.x = a.x - b.x * 0.03125f;  v.y = a.y - b.y * 0.03125f;
            v.z = a.z - b.z * 0.03125f;  v.w = a.w - b.w * 0.03125f;
        } else if (seg == 2) {
            v = wih[(512 + j) * 64 + c4];
        } else {
            v = whh[(512 + j) * 64 + c4];
        }
        dst = wc2_f + t;
    }
    else return;
    uint2 o;
    o.x = pack_h2(v.x, v.y);
    o.y = pack_h2(v.z, v.w);
    *dst = o;
}

// fobs_W transpose -> fp16: fwT[m*256+j] = fw[j*256+m]
__global__ void transpose_fw(const float* __restrict__ fw, __half* __restrict__ fwT)
{
    const int idx = blockIdx.x * blockDim.x + threadIdx.x;  // over 65536
    const int m = idx >> 8, j = idx & 255;
    fwT[idx] = __float2half_rn(fw[j * HD + m]);
}

// Build interleaved w23: row nr -> seg0: fobs_W[j] (fp32->fp16);
// seg1..3: wcomb row (seg-1)*256+j (fp16 copy). One block per row, 64 threads.
__global__ void build_w23(const float* __restrict__ fw, const uint2* __restrict__ wcomb,
                          uint2* __restrict__ w23)
{
    const int nr = blockIdx.x;                 // 0..1023
    const int c  = threadIdx.x;                // 0..63 (uint2 = 4 halves)
    const int seg = (nr >> 5) & 3;
    const int j = (nr >> 7) * 32 + (nr & 31);
    uint2 o;
    if (seg == 0) {
        const float* row = fw + (size_t)j * HD + c * 4;
        o.x = pack_h2(row[0], row[1]);
        o.y = pack_h2(row[2], row[3]);
    } else {
        o = wcomb[(size_t)((seg - 1) * 256 + j) * 64 + c];
    }
    w23[(size_t)nr * 64 + c] = o;
}

// Parallel bias builder (interleaved layouts).
//  blocks 0..95 : bias23 Wcomb rows: r=0..767 (warp per row)
//                 nr = (j>>5)*128 + (seg_src+1)*32 + (j&31), j=r&255, seg_src=r>>8
//  blocks 96..99: bias2 (interleaved) + bias23 seg0 = fobs_b
__global__ void biases_kernel(const float* __restrict__ b_ih, const float* __restrict__ b_hh,
                              const float* __restrict__ fobs_b, const float* __restrict__ W_hh,
                              float* __restrict__ bias2, float* __restrict__ bias23)
{
    const int blk = blockIdx.x;
    if (blk < 96) {
        const int warp = threadIdx.x >> 5, lane = threadIdx.x & 31;
        const int r = blk * 8 + warp;          // 0..767
        const float* row = W_hh + (size_t)r * HD;
        float s = 0.f;
#pragma unroll
        for (int j = lane; j < HD; j += 32) s += row[j] * fobs_b[j];
#pragma unroll
        for (int o = 16; o > 0; o >>= 1) s += __shfl_down_sync(0xffffffffu, s, o);
        if (lane == 0) {
            const int seg = r >> 8, j = r & 255;
            const int nr = (j >> 5) * 128 + (seg + 1) * 32 + (j & 31);
            bias23[nr] = s + b_hh[r];
        }
    } else {
        const int i = (blk - 96) * 256 + threadIdx.x;  // 0..1023
        if (i < H4) {
            const int seg = (i >> 5) & 3;
            const int j = (i >> 7) * 32 + (i & 31);
            float v;
            if (seg == 0)      v = b_ih[j] + b_hh[j];
            else if (seg == 1) v = b_ih[256 + j] + b_hh[256 + j];
            else if (seg == 2) v = 0.f;
            else               v = b_hh[512 + j];
            bias2[i] = v;
            if (i < 256) {
                const int nr = (i >> 5) * 128 + (i & 31);
                bias23[nr] = fobs_b[i];
            }
        }
    }
}

// out[i] = dec_b[0]  (decoder bias pre-seeded; FUSE1 atomically accumulates)
__global__ void out_init(float* __restrict__ out, const float* __restrict__ dec_b)
{
    const int i = blockIdx.x * blockDim.x + threadIdx.x;
    if (i < NROWS) out[i] = dec_b[0];
}

// ---------------------------------------------------------------------------
// fp16 GEMM (R13 mainloop): cp.async 3-stage, 1 sync/chunk, fragment dbuf.
// CTA tile 128x128, KC=64, 8 warps (2m x 4n, warp 64x32), 2 CTAs/SM.
// MODE: 0=WHALF, 1=WF32, 2=RELU+WHALF, 3=FUSE gates0+S, 4=FUSE gates1+decoder
// FUSE modes require interleaved weights: col block = [s0|s1|s2|s3] x 32 j's.
// ---------------------------------------------------------------------------
#define ST_AH 0
#define ST_WH 16384
#define ST_SZ 32768
#define SM_TOTAL (3 * ST_SZ)
#define TS 132   // smem staging tile stride (floats)

template <int MODE>
__global__ __launch_bounds__(256, 2)
void mma_gemmh(const __half* __restrict__ Ag, const __half* __restrict__ Wg,
               const float* __restrict__ bias, float* __restrict__ Cf,
               __half* __restrict__ Ch,
               const float* __restrict__ xb,     // FUSE: b_ih
               const float* __restrict__ sgp,    // FUSE1: Sg
               __half* __restrict__ h1rw,        // FUSE0: h1 out; FUSE1: h1 in
               __half* __restrict__ sfp,         // FUSE0: S out
               const float* __restrict__ dwp,    // FUSE1: dec_W
               float* __restrict__ outp,         // FUSE1: out
               int K, int M)
{
    extern __shared__ char smem[];
    const uint32_t sb = smem_to_u32(smem);
    const int tid  = threadIdx.x;
    const int wid  = tid >> 5;
    const int lane = tid & 31;
    const int row0 = blockIdx.y * 128;
    const int col0 = blockIdx.x * 128;
    const int wm0  = (wid >> 2) * 64;
    const int wn0  = (wid & 3) * 32;

    const int a_row = wm0 + (lane & 15);
    const int a_kb  = ((lane >> 4) & 1) * 16;
    const int b_row = wn0 + (lane & 7);
    const int b_kb  = ((lane >> 3) & 1) * 16;

    const int r0_ = tid >> 3, k00 = (tid & 7) * 8;
    const uint32_t sw0 = SMEM_SWIZZLE_128B((uint32_t)(r0_ * 128 + k00 * 2));
    const __half* pA0 = Ag + (size_t)(row0 + r0_) * K + k00;
    const __half* pW0 = Wg + (size_t)(col0 + r0_) * K + k00;
    const size_t itK = (size_t)32 * K;

    float acc[4][4][4];
#pragma unroll
    for (int i = 0; i < 4; i++)
#pragma unroll
        for (int j = 0; j < 4; j++)
#pragma unroll
            for (int q = 0; q < 4; q++) acc[i][j][q] = 0.f;

    const int nch = K >> 6;

#pragma unroll
    for (int it = 0; it < 4; it++) {
        cp16(sb + ST_AH + sw0 + it * 4096, pA0 + it * itK);
        cp16(sb + ST_WH + sw0 + it * 4096, pW0 + it * itK);
    }
    CP_COMMIT();
    if (nch > 1) {
#pragma unroll
        for (int it = 0; it < 4; it++) {
            cp16(sb + ST_SZ + ST_AH + sw0 + it * 4096, pA0 + it * itK + 64);
            cp16(sb + ST_SZ + ST_WH + sw0 + it * 4096, pW0 + it * itK + 64);
        }
    }
    CP_COMMIT();

    uint32_t Af[2][4][4], Bf[2][4][2];

    for (int ch = 0; ch < nch; ch++) {
        const uint32_t sbase = sb + (uint32_t)(ch % 3) * ST_SZ;
        if (ch + 1 < nch) { CP_WAIT(1); } else { CP_WAIT(0); }
        __syncthreads();
        if (ch + 2 < nch) {
            const uint32_t nbase = sb + (uint32_t)((ch + 2) % 3) * ST_SZ;
            const int koff = (ch + 2) * 64;
#pragma unroll
            for (int it = 0; it < 4; it++) {
                cp16(nbase + ST_AH + sw0 + it * 4096, pA0 + it * itK + koff);
                cp16(nbase + ST_WH + sw0 + it * 4096, pW0 + it * itK + koff);
            }
            CP_COMMIT();
        } else {
            CP_COMMIT();
        }

#pragma unroll
        for (int fm = 0; fm < 4; fm++) {
            uint32_t loc = SMEM_SWIZZLE_128B((uint32_t)((a_row + fm * 16) * 128 + a_kb));
            ldm_x4(Af[0][fm], sbase + ST_AH + loc);
        }
#pragma unroll
        for (int fn = 0; fn < 4; fn++) {
            uint32_t loc = SMEM_SWIZZLE_128B((uint32_t)((b_row + fn * 8) * 128 + b_kb));
            ldm_x2(Bf[0][fn], sbase + ST_WH + loc);
        }

#pragma unroll
        for (int ks = 0; ks < 4; ks++) {
            const int cur = ks & 1, nxt = cur ^ 1;
            if (ks < 3) {
#pragma unroll
                for (int fm = 0; fm < 4; fm++) {
                    uint32_t loc = SMEM_SWIZZLE_128B(
                        (uint32_t)((a_row + fm * 16) * 128 + (ks + 1) * 32 + a_kb));
                    ldm_x4(Af[nxt][fm], sbase + ST_AH + loc);
                }
#pragma unroll
                for (int fn = 0; fn < 4; fn++) {
                    uint32_t loc = SMEM_SWIZZLE_128B(
                        (uint32_t)((b_row + fn * 8) * 128 + (ks + 1) * 32 + b_kb));
                    ldm_x2(Bf[nxt][fn], sbase + ST_WH + loc);
                }
            }
#pragma unroll
            for (int fm = 0; fm < 4; fm++)
#pragma unroll
                for (int fn = 0; fn < 4; fn++)
                    mma_f16(acc[fm][fn], Af[cur][fm][0], Af[cur][fm][1], Af[cur][fm][2],
                            Af[cur][fm][3], Bf[cur][fn][0], Bf[cur][fn][1]);
        }
    }

    const int gid  = lane >> 2;
    const int tid4 = lane & 3;

    if (MODE <= 2) {
#pragma unroll
        for (int fn = 0; fn < 4; fn++) {
            const int col = col0 + wn0 + fn * 8 + 2 * tid4;
            const float b0 = bias[col], b1 = bias[col + 1];
#pragma unroll
            for (int fm = 0; fm < 4; fm++) {
                const int rlo = row0 + wm0 + fm * 16 + gid;
                float2 v0, v1;
                v0.x = acc[fm][fn][0] + b0;  v0.y = acc[fm][fn][1] + b1;
                v1.x = acc[fm][fn][2] + b0;  v1.y = acc[fm][fn][3] + b1;
                if (MODE == 2) {
                    v0.x = fmaxf(v0.x, 0.f); v0.y = fmaxf(v0.y, 0.f);
                    v1.x = fmaxf(v1.x, 0.f); v1.y = fmaxf(v1.y, 0.f);
                }
                if (MODE == 1) {
                    *reinterpret_cast<float2*>(Cf + (size_t)rlo * M + col)       = v0;
                    *reinterpret_cast<float2*>(Cf + (size_t)(rlo + 8) * M + col) = v1;
                } else {
                    *reinterpret_cast<uint32_t*>(Ch + (size_t)rlo * M + col)       = pack_h2(v0.x, v0.y);
                    *reinterpret_cast<uint32_t*>(Ch + (size_t)(rlo + 8) * M + col) = pack_h2(v1.x, v1.y);
                }
            }
        }
    } else {
        // ---- fused epilogue: stage tile + bias into fp32 smem ----
        __syncthreads();   // all warps done reading mainloop stages
        float* T = reinterpret_cast<float*>(smem);
        float* Ssm = T + 128 * TS;
#pragma unroll
        for (int fn = 0; fn < 4; fn++) {
            const int cl = wn0 + fn * 8 + 2 * tid4;
            const float b0 = bias[col0 + cl], b1 = bias[col0 + cl + 1];
#pragma unroll
            for (int fm = 0; fm < 4; fm++) {
                const int rl = wm0 + fm * 16 + gid;
                T[rl * TS + cl]           = acc[fm][fn][0] + b0;
                T[rl * TS + cl + 1]       = acc[fm][fn][1] + b1;
                T[(rl + 8) * TS + cl]     = acc[fm][fn][2] + b0;
                T[(rl + 8) * TS + cl + 1] = acc[fm][fn][3] + b1;
            }
        }
        if (MODE == 3 && tid < 128) Ssm[tid] = 0.f;
        __syncthreads();

        const int jj = tid & 31, g = tid >> 5;
        const int jglob = blockIdx.x * 32 + jj;

        if (MODE == 3) {
            const float bir = xb[jglob], biz = xb[256 + jglob], bin = xb[512 + jglob];
            float sacc[4] = {0.f, 0.f, 0.f, 0.f};
#pragma unroll
            for (int k = 0; k < 16; k++) {
                const int r = g + 8 * k;
                float hh = T[r * TS + jj];
                float gr = T[r * TS + 32 + jj];
                float gz = T[r * TS + 64 + jj];
                float gn = T[r * TS + 96 + jj];
                float rr = sigmoidf_(bir + gr), z = sigmoidf_(biz + gz);
                float n = tanhf(bin + rr * gn);
                float o = (1.f - z) * n + z * hh;
                h1rw[(size_t)(row0 + r) * HD + jglob] = __float2half_rn(o);
                sacc[k >> 2] += o;
            }
#pragma unroll
            for (int bb = 0; bb < 4; bb++) atomicAdd(&Ssm[bb * 32 + jj], sacc[bb]);
            __syncthreads();
            if (tid < 128)
                sfp[(size_t)(blockIdx.y * 4 + (tid >> 5)) * HD + blockIdx.x * 32 + (tid & 31)] =
                    __float2half_rn(Ssm[tid]);
        } else {
            const float bin = xb[512 + jglob];
            const float dw  = dwp[jglob];
            const float inv = 1.f / 32.f;
#pragma unroll
            for (int k = 0; k < 16; k++) {
                const int r = g + 8 * k;
                const int rg = row0 + r;
                const int b = rg >> 5;
                float rzr  = T[r * TS + jj];
                float rzz  = T[r * TS + 32 + jj];
                float gihn = T[r * TS + 64 + jj];
                float hn   = T[r * TS + 96 + jj];
                float sgr = sgp[(size_t)b * H3 + jglob];
                float sgz = sgp[(size_t)b * H3 + 256 + jglob];
                float sgn = sgp[(size_t)b * H3 + 512 + jglob];
                float rr = sigmoidf_(rzr + sgr * inv), z = sigmoidf_(rzz + sgz * inv);
                float n = tanhf((sgn - gihn) * inv + bin + rr * hn);
                float hp = __half2float(h1rw[(size_t)rg * HD + jglob]);
                float p = ((1.f - z) * n + z * hp) * dw;
#pragma unroll
                for (int o = 16; o > 0; o >>= 1) p += __shfl_down_sync(0xffffffffu, p, o);
                if (jj == 0) atomicAdd(outp + rg, p);
            }
        }
    }
}

// ---------------------------------------------------------------------------
// Launch
// ---------------------------------------------------------------------------
extern "C" void kernel_launch(void* const* d_in, const int* in_sizes, int n_in,
                              void* d_out, int out_size)
{
    const float* obs    = (const float*)d_in[0];
    const float* enc_W  = (const float*)d_in[2];
    const float* enc_b  = (const float*)d_in[3];
    const float* fobs_W = (const float*)d_in[4];
    const float* fobs_b = (const float*)d_in[5];
    const float* W_ih   = (const float*)d_in[6];
    const float* b_ih   = (const float*)d_in[7];
    const float* W_hh   = (const float*)d_in[8];
    const float* b_hh   = (const float*)d_in[9];
    const float* dec_W  = (const float*)d_in[10];
    const float* dec_b  = (const float*)d_in[11];
    float* out = (float*)d_out;

    float *sg, *bias2, *bias23, *zero_bias;
    cudaGetSymbolAddress((void**)&sg,     g_sg);
    cudaGetSymbolAddress((void**)&bias2,  g_bias2);
    cudaGetSymbolAddress((void**)&bias23, g_bias23);
    cudaGetSymbolAddress((void**)&zero_bias, g_zero_bias);

    void *obs_f, *e_f, *h1_f, *S_f, *ew_f, *fwT_f, *wcomb_f, *w23_f, *wih_f, *whh_f, *wc2_f;
    cudaGetSymbolAddress(&obs_f,  g_obs_f);
    cudaGetSymbolAddress(&e_f,    g_e_f);
    cudaGetSymbolAddress(&h1_f,   g_h1_f);
    cudaGetSymbolAddress(&S_f,    g_S_f);
    cudaGetSymbolAddress(&ew_f,   g_ew_f);
    cudaGetSymbolAddress(&fwT_f,  g_fwT_f);
    cudaGetSymbolAddress(&wcomb_f, g_wcomb_f);
    cudaGetSymbolAddress(&w23_f,  g_w23_f);
    cudaGetSymbolAddress(&wih_f,  g_wih_f);
    cudaGetSymbolAddress(&whh_f,  g_whh_f);
    cudaGetSymbolAddress(&wc2_f,  g_wc2_f);

    cudaFuncSetAttribute(mma_gemmh<0>, cudaFuncAttributeMaxDynamicSharedMemorySize, SM_TOTAL);
    cudaFuncSetAttribute(mma_gemmh<1>, cudaFuncAttributeMaxDynamicSharedMemorySize, SM_TOTAL);
    cudaFuncSetAttribute(mma_gemmh<2>, cudaFuncAttributeMaxDynamicSharedMemorySize, SM_TOTAL);
    cudaFuncSetAttribute(mma_gemmh<3>, cudaFuncAttributeMaxDynamicSharedMemorySize, SM_TOTAL);
    cudaFuncSetAttribute(mma_gemmh<4>, cudaFuncAttributeMaxDynamicSharedMemorySize, SM_TOTAL);

    typedef const __half* hfp;
    typedef __half* hfpm;

    convert_h<<<(NROWS * DIN / 4 + 255) / 256, 256>>>((const float4*)obs, (uint2*)obs_f, NROWS * DIN / 4);
    convert_weights<<<(172032 + 255) / 256, 256>>>(
        (const float4*)enc_W, (const float4*)W_ih, (const float4*)W_hh,
        (uint2*)ew_f, (uint2*)wih_f, (uint2*)whh_f, (uint2*)wc2_f);
    transpose_fw<<<(HD * HD + 255) / 256, 256>>>(fobs_W, (hfpm)fwT_f);
    biases_kernel<<<100, 256>>>(b_ih, b_hh, fobs_b, W_hh, bias2, bias23);
    out_init<<<NROWS / 256, 256>>>(out, dec_b);

    const dim3 blk(256);
    const int rowBlocks = NROWS / 128;  // 512

    // 0) Wcomb = W_hh @ fobs_W  (768x256, K=256) -> wcomb_f
    mma_gemmh<0><<<dim3(2, H3 / 128), blk, SM_TOTAL>>>(
        (hfp)whh_f, (hfp)fwT_f, zero_bias, nullptr, (hfpm)wcomb_f,
        nullptr, nullptr, nullptr, nullptr, nullptr, nullptr, HD, HD);
    // 0b) build interleaved w23 from fobs_W + Wcomb
    build_w23<<<H4, 64>>>(fobs_W, (const uint2*)wcomb_f, (uint2*)w23_f);
    // 1) e = relu(obs @ enc_W^T + enc_b) -> fp16
    mma_gemmh<2><<<dim3(2, rowBlocks), blk, SM_TOTAL>>>(
        (hfp)obs_f, (hfp)ew_f, enc_b, nullptr, (hfpm)e_f,
        nullptr, nullptr, nullptr, nullptr, nullptr, nullptr, DIN, HD);
    // 2+3+4) [h|gh] GEMM with fused gates0 + agent sum -> h1_f, S_f  (M=1024)
    mma_gemmh<3><<<dim3(8, rowBlocks), blk, SM_TOTAL>>>(
        (hfp)e_f, (hfp)w23_f, bias23, nullptr, nullptr,
        b_ih, nullptr, (hfpm)h1_f, (hfpm)S_f, nullptr, nullptr, HD, H4);
    // 5) Sg = S @ W_ih^T (zero bias) -> fp32
    mma_gemmh<1><<<dim3(6, NB / 128), blk, SM_TOTAL>>>(
        (hfp)S_f, (hfp)wih_f, zero_bias, sg, nullptr,
        nullptr, nullptr, nullptr, nullptr, nullptr, nullptr, HD, H3);
    // 6+7) gc2 GEMM with fused gates1 + decoder -> atomic out  (M=1024)
    mma_gemmh<4><<<dim3(8, rowBlocks), blk, SM_TOTAL>>>(
        (hfp)h1_f, (hfp)wc2_f, bias2, nullptr, nullptr,
        b_ih, sg, (hfpm)h1_f, nullptr, dec_W, out, HD, H4);
}